// round 1
// baseline (speedup 1.0000x reference)
#include <cuda_runtime.h>
#include <cstdint>

#define NUM_T   128
#define DIM     1024
#define NC      512
#define TOPK    8
#define VPC     256
#define VOCAB   131072
#define TPB     4      // tokens per block in scores kernel

// scratch: top-8 centroid indices per token
__device__ int g_topk[NUM_T * TOPK];

// ---------------------------------------------------------------------------
// Fill output with -FLT_MAX (jnp.finfo(float32).min) using float4 stores
// ---------------------------------------------------------------------------
__global__ void fill_kernel(float4* __restrict__ out, int n4) {
    const float v = __int_as_float(0xff7fffff);  // -FLT_MAX
    const float4 f = make_float4(v, v, v, v);
    for (int i = blockIdx.x * blockDim.x + threadIdx.x; i < n4;
         i += gridDim.x * blockDim.x)
        out[i] = f;
}

// ---------------------------------------------------------------------------
// Centroid scores (H @ C^T) for 4 tokens per block + per-token top-8
// ---------------------------------------------------------------------------
__global__ void scores_topk_kernel(const float* __restrict__ H,
                                   const float* __restrict__ C) {
    __shared__ float4 Hs4[TPB * (DIM / 4)];   // 16 KB
    __shared__ float  sc[TPB][NC];            // 8 KB
    __shared__ float  redv[256];
    __shared__ int    redi[256];

    const int tid  = threadIdx.x;
    const int lane = tid & 31;
    const int warp = tid >> 5;
    const int t0   = blockIdx.x * TPB;

    const float4* H4 = (const float4*)H;
    for (int i = tid; i < TPB * (DIM / 4); i += 256)
        Hs4[i] = H4[t0 * (DIM / 4) + i];
    __syncthreads();

    const float4* C4 = (const float4*)C;
    for (int c = warp; c < NC; c += 8) {
        float a0 = 0.f, a1 = 0.f, a2 = 0.f, a3 = 0.f;
        #pragma unroll
        for (int j = 0; j < DIM / 128; j++) {
            const float4 cv = C4[(size_t)c * (DIM / 4) + lane + 32 * j];
            const float4 h0 = Hs4[0 * (DIM / 4) + lane + 32 * j];
            const float4 h1 = Hs4[1 * (DIM / 4) + lane + 32 * j];
            const float4 h2 = Hs4[2 * (DIM / 4) + lane + 32 * j];
            const float4 h3 = Hs4[3 * (DIM / 4) + lane + 32 * j];
            a0 += cv.x * h0.x + cv.y * h0.y + cv.z * h0.z + cv.w * h0.w;
            a1 += cv.x * h1.x + cv.y * h1.y + cv.z * h1.z + cv.w * h1.w;
            a2 += cv.x * h2.x + cv.y * h2.y + cv.z * h2.z + cv.w * h2.w;
            a3 += cv.x * h3.x + cv.y * h3.y + cv.z * h3.z + cv.w * h3.w;
        }
        #pragma unroll
        for (int s = 16; s; s >>= 1) {
            a0 += __shfl_xor_sync(0xffffffffu, a0, s);
            a1 += __shfl_xor_sync(0xffffffffu, a1, s);
            a2 += __shfl_xor_sync(0xffffffffu, a2, s);
            a3 += __shfl_xor_sync(0xffffffffu, a3, s);
        }
        if (lane == 0) {
            sc[0][c] = a0; sc[1][c] = a1; sc[2][c] = a2; sc[3][c] = a3;
        }
    }
    __syncthreads();

    // per-token top-8 (argmax 8 rounds, lowest-index tie-break like lax.top_k)
    for (int tk = 0; tk < TPB; tk++) {
        for (int r = 0; r < TOPK; r++) {
            float v0 = sc[tk][tid];
            float v1 = sc[tk][tid + 256];
            float bv; int bi;
            if (v1 > v0) { bv = v1; bi = tid + 256; }
            else         { bv = v0; bi = tid; }
            redv[tid] = bv; redi[tid] = bi;
            __syncthreads();
            for (int s = 128; s; s >>= 1) {
                if (tid < s) {
                    if (redv[tid + s] > redv[tid] ||
                        (redv[tid + s] == redv[tid] && redi[tid + s] < redi[tid])) {
                        redv[tid] = redv[tid + s];
                        redi[tid] = redi[tid + s];
                    }
                }
                __syncthreads();
            }
            if (tid == 0) {
                const int best = redi[0];
                g_topk[(t0 + tk) * TOPK + r] = best;
                sc[tk][best] = __int_as_float(0xff800000);  // -inf
            }
            __syncthreads();
        }
    }
}

// ---------------------------------------------------------------------------
// Logits for selected rows + scatter. Block = (token, k) pair; warp per row.
// ---------------------------------------------------------------------------
__global__ void logits_kernel(const float* __restrict__ H,
                              const float* __restrict__ W,
                              const int* __restrict__ ord,
                              float* __restrict__ out) {
    __shared__ float4 Hs4[DIM / 4];   // 4 KB

    const int t    = blockIdx.x >> 3;
    const int k    = blockIdx.x & 7;
    const int tid  = threadIdx.x;
    const int lane = tid & 31;
    const int warp = tid >> 5;

    const float4* H4 = (const float4*)H;
    Hs4[tid] = H4[t * (DIM / 4) + tid];
    __syncthreads();

    const int c = g_topk[t * TOPK + k];
    const float4* W4 = (const float4*)W;

    for (int r = warp; r < VPC; r += 8) {
        const int vid = ord[c * VPC + r];
        const float4* Wr = W4 + (size_t)vid * (DIM / 4);
        float s = 0.f;
        #pragma unroll
        for (int j = 0; j < DIM / 128; j++) {
            const float4 w = Wr[lane + 32 * j];
            const float4 h = Hs4[lane + 32 * j];
            s += w.x * h.x + w.y * h.y + w.z * h.z + w.w * h.w;
        }
        #pragma unroll
        for (int sft = 16; sft; sft >>= 1)
            s += __shfl_xor_sync(0xffffffffu, s, sft);
        if (lane == 0)
            out[(size_t)t * VOCAB + vid] = s;
    }
}

// ---------------------------------------------------------------------------
extern "C" void kernel_launch(void* const* d_in, const int* in_sizes, int n_in,
                              void* d_out, int out_size) {
    const float* H   = (const float*)d_in[0];   // (128, 1024)
    const float* W   = (const float*)d_in[1];   // (131072, 1024)
    const float* C   = (const float*)d_in[2];   // (512, 1024)
    const int*   ord = (const int*)d_in[3];     // (131072,)
    float* out = (float*)d_out;

    const int n4 = out_size / 4;  // 4,194,304 float4
    fill_kernel<<<2048, 256>>>((float4*)out, n4);
    scores_topk_kernel<<<NUM_T / TPB, 256>>>(H, C);
    logits_kernel<<<NUM_T * TOPK, 256>>>(H, W, ord, out);
}

// round 4
// speedup vs baseline: 2.3611x; 2.3611x over previous
#include <cuda_runtime.h>
#include <cstdint>

#define NUM_T   128
#define DIM     1024
#define D4      (DIM / 4)
#define NC      512
#define TOPK    8
#define VPC     256
#define VOCAB   131072
#define TILE    8       // token tile cached in smem in logits kernel

// scratch (__device__ globals; no allocations allowed)
__device__ float g_scores[NUM_T * NC];          // 256 KB
__device__ int   g_topk[NUM_T * TOPK];
__device__ int   g_cnt[NC];
__device__ int   g_toklist[NC * NUM_T];         // 256 KB

// ---------------------------------------------------------------------------
// Fill output with -FLT_MAX (jnp.finfo(float32).min)
// ---------------------------------------------------------------------------
__global__ void fill_kernel(float4* __restrict__ out, int n4) {
    const float v = __int_as_float(0xff7fffff);  // -FLT_MAX
    const float4 f = make_float4(v, v, v, v);
    for (int i = blockIdx.x * blockDim.x + threadIdx.x; i < n4;
         i += gridDim.x * blockDim.x)
        out[i] = f;
}

// ---------------------------------------------------------------------------
// Centroid scores: block = 4 tokens x 128 centroids. grid (32, 4).
// ---------------------------------------------------------------------------
__global__ void scores_kernel(const float* __restrict__ H,
                              const float* __restrict__ C) {
    __shared__ float4 Hs4[4 * D4];   // 16 KB

    const int tid  = threadIdx.x;
    const int lane = tid & 31;
    const int warp = tid >> 5;
    const int t0   = blockIdx.x * 4;
    const int c0   = blockIdx.y * 128;

    const float4* H4 = (const float4*)H;
    for (int i = tid; i < 4 * D4; i += 256)
        Hs4[i] = H4[t0 * D4 + i];
    __syncthreads();

    const float4* C4 = (const float4*)C;
    for (int c = c0 + warp; c < c0 + 128; c += 8) {
        float a0 = 0.f, a1 = 0.f, a2 = 0.f, a3 = 0.f;
        #pragma unroll
        for (int j = 0; j < DIM / 128; j++) {
            const float4 cv = C4[(size_t)c * D4 + lane + 32 * j];
            const float4 h0 = Hs4[0 * D4 + lane + 32 * j];
            const float4 h1 = Hs4[1 * D4 + lane + 32 * j];
            const float4 h2 = Hs4[2 * D4 + lane + 32 * j];
            const float4 h3 = Hs4[3 * D4 + lane + 32 * j];
            a0 += cv.x * h0.x + cv.y * h0.y + cv.z * h0.z + cv.w * h0.w;
            a1 += cv.x * h1.x + cv.y * h1.y + cv.z * h1.z + cv.w * h1.w;
            a2 += cv.x * h2.x + cv.y * h2.y + cv.z * h2.z + cv.w * h2.w;
            a3 += cv.x * h3.x + cv.y * h3.y + cv.z * h3.z + cv.w * h3.w;
        }
        #pragma unroll
        for (int s = 16; s; s >>= 1) {
            a0 += __shfl_xor_sync(0xffffffffu, a0, s);
            a1 += __shfl_xor_sync(0xffffffffu, a1, s);
            a2 += __shfl_xor_sync(0xffffffffu, a2, s);
            a3 += __shfl_xor_sync(0xffffffffu, a3, s);
        }
        if (lane == 0) {
            g_scores[(t0 + 0) * NC + c] = a0;
            g_scores[(t0 + 1) * NC + c] = a1;
            g_scores[(t0 + 2) * NC + c] = a2;
            g_scores[(t0 + 3) * NC + c] = a3;
        }
    }
}

// ---------------------------------------------------------------------------
// Top-8 per token: warp per token, scores register-resident.
// Tie-break: lowest index wins (matches jax.lax.top_k).
// grid 32 blocks x 128 threads (4 warps).
// ---------------------------------------------------------------------------
__global__ void topk_kernel() {
    const int t    = blockIdx.x * 4 + (threadIdx.x >> 5);
    const int lane = threadIdx.x & 31;
    const float NEG_INF = __int_as_float(0xff800000);

    float sc[16];
    #pragma unroll
    for (int j = 0; j < 16; j++)
        sc[j] = g_scores[t * NC + lane * 16 + j];

    #pragma unroll
    for (int r = 0; r < TOPK; r++) {
        float bv = sc[0];
        int   bi = lane * 16;
        #pragma unroll
        for (int j = 1; j < 16; j++) {
            if (sc[j] > bv) { bv = sc[j]; bi = lane * 16 + j; }
        }
        #pragma unroll
        for (int s = 16; s; s >>= 1) {
            const float ov = __shfl_xor_sync(0xffffffffu, bv, s);
            const int   oi = __shfl_xor_sync(0xffffffffu, bi, s);
            if (ov > bv || (ov == bv && oi < bi)) { bv = ov; bi = oi; }
        }
        if (lane == (bi >> 4)) sc[bi & 15] = NEG_INF;
        if (lane == 0) g_topk[t * TOPK + r] = bi;
    }
}

// ---------------------------------------------------------------------------
// Build inverted index: centroid -> list of tokens that selected it.
// 1 block, 512 threads.
// ---------------------------------------------------------------------------
__global__ void build_kernel() {
    const int tid = threadIdx.x;
    g_cnt[tid] = 0;
    __syncthreads();
    if (tid < NUM_T) {
        #pragma unroll
        for (int k = 0; k < TOPK; k++) {
            const int c   = g_topk[tid * TOPK + k];
            const int pos = atomicAdd(&g_cnt[c], 1);
            g_toklist[c * NUM_T + pos] = tid;
        }
    }
}

// ---------------------------------------------------------------------------
// Centroid-major logits + scatter.
// Block = (centroid, 64-row chunk). grid = 512*4 = 2048 blocks, 256 threads.
// Each W row is read exactly once from DRAM; H rows for the selecting tokens
// are staged in smem (TILE at a time).
// ---------------------------------------------------------------------------
__global__ void logits_kernel(const float* __restrict__ H,
                              const float* __restrict__ W,
                              const int* __restrict__ ord,
                              float* __restrict__ out) {
    __shared__ float4 Hs[TILE][D4];   // 32 KB
    __shared__ int    toks[TILE];

    const int c     = blockIdx.x >> 2;
    const int chunk = blockIdx.x & 3;
    const int nt    = g_cnt[c];
    if (nt == 0) return;

    const int tid  = threadIdx.x;
    const int lane = tid & 31;
    const int warp = tid >> 5;
    const int r0   = chunk * 64;

    const float4* H4 = (const float4*)H;
    const float4* W4 = (const float4*)W;

    for (int base = 0; base < nt; base += TILE) {
        const int m = min(TILE, nt - base);
        if (tid < m) toks[tid] = g_toklist[c * NUM_T + base + tid];
        __syncthreads();
        for (int i = tid; i < m * D4; i += 256) {
            const int ti = i >> 8;          // i / 256
            const int e  = i & (D4 - 1);    // i % 256
            Hs[ti][e] = H4[(size_t)toks[ti] * D4 + e];
        }
        __syncthreads();

        for (int r = r0 + warp; r < r0 + 64; r += 8) {
            const int vid = __ldg(&ord[c * VPC + r]);
            float4 w[8];
            #pragma unroll
            for (int j = 0; j < 8; j++)
                w[j] = W4[(size_t)vid * D4 + lane + 32 * j];

            for (int i = 0; i < m; i++) {
                float s = 0.f;
                #pragma unroll
                for (int j = 0; j < 8; j++) {
                    const float4 h = Hs[i][lane + 32 * j];
                    s += w[j].x * h.x + w[j].y * h.y +
                         w[j].z * h.z + w[j].w * h.w;
                }
                #pragma unroll
                for (int sft = 16; sft; sft >>= 1)
                    s += __shfl_xor_sync(0xffffffffu, s, sft);
                if (lane == 0)
                    out[(size_t)toks[i] * VOCAB + vid] = s;
            }
        }
        __syncthreads();
    }
}

// ---------------------------------------------------------------------------
extern "C" void kernel_launch(void* const* d_in, const int* in_sizes, int n_in,
                              void* d_out, int out_size) {
    const float* H   = (const float*)d_in[0];   // (128, 1024)
    const float* W   = (const float*)d_in[1];   // (131072, 1024)
    const float* C   = (const float*)d_in[2];   // (512, 1024)
    const int*   ord = (const int*)d_in[3];     // (131072,)
    float* out = (float*)d_out;

    const int n4 = out_size / 4;
    fill_kernel<<<2048, 256>>>((float4*)out, n4);
    scores_kernel<<<dim3(NUM_T / 4, NC / 128), 256>>>(H, C);
    topk_kernel<<<NUM_T / 4, 128>>>();
    build_kernel<<<1, NC>>>();
    logits_kernel<<<NC * 4, 256>>>(H, W, ord, out);
}